// round 9
// baseline (speedup 1.0000x reference)
#include <cuda_runtime.h>
#include <cuda_bf16.h>
#include <cstdint>

// SeparationLoss: mean over B of sum_{i!=j} max(0, thr2 - ||kp_i - kp_j||^2)
// Input: batched_kps [B, 17, 3] f32 (B = 131072). Output: scalar f32.
//
// R9: two-pass register tiling. Pass1: joints 0-8 in regs (intra 36 pairs) +
// joints 9-16 streamed from SMEM (72 cross pairs). Pass2: joints 9-16 in regs
// (intra 28 pairs). Halves live registers (~55 vs 80) at ~equal op count ->
// 8 blocks/SM, 32 warps (occ 50% vs 33%), ONE wave (grid 1024 <= 1184).
// Gram identity retained (5 fma-class/pair). Bulk-copy staging + fused
// last-block-done reduction retained.

#define J 17
#define ROW_F 51                    // 17*3 floats per row
#define ROWS_PER_BLOCK 128
#define THREADS 128
#define TILE_BYTES (ROWS_PER_BLOCK * ROW_F * 4)   // 26112
#define NBLOCKS_MAX 8192

__device__ __align__(16) float g_partials[NBLOCKS_MAX];
__device__ unsigned int g_done_count;   // zero-init; atomicInc wrap self-resets

__device__ __forceinline__ uint32_t smem_u32(const void* p) {
    uint32_t a;
    asm("{ .reg .u64 t; cvta.to.shared.u64 t, %1; cvt.u32.u64 %0, t; }"
        : "=r"(a) : "l"(p));
    return a;
}

__global__ __launch_bounds__(THREADS, 8)   // 64-reg cap; ~55 demand. 8 blocks/SM.
void sep_loss_fused(const float* __restrict__ kps, int B, int nblocks,
                    float invB, float* __restrict__ out) {
    __shared__ __align__(16) float s[ROWS_PER_BLOCK * ROW_F];   // 26112 B
    __shared__ __align__(8)  unsigned long long mbar;
    __shared__ float wsum[THREADS / 32];
    __shared__ bool  isLast;

    const int tid = threadIdx.x;
    const int rowBase = blockIdx.x * ROWS_PER_BLOCK;
    const int rowsHere = min(ROWS_PER_BLOCK, B - rowBase);

    if (rowsHere == ROWS_PER_BLOCK) {
        // ---- single bulk copy per block ----
        const uint32_t mb = smem_u32(&mbar);
        if (tid == 0)
            asm volatile("mbarrier.init.shared.b64 [%0], %1;"
                         :: "r"(mb), "r"(1) : "memory");
        __syncthreads();
        if (tid == 0) {
            asm volatile("mbarrier.arrive.expect_tx.shared.b64 _, [%0], %1;"
                         :: "r"(mb), "r"((uint32_t)TILE_BYTES) : "memory");
            asm volatile(
                "cp.async.bulk.shared::cta.global.mbarrier::complete_tx::bytes "
                "[%0], [%1], %2, [%3];"
                :: "r"(smem_u32(s)), "l"(kps + (size_t)rowBase * ROW_F),
                   "r"((uint32_t)TILE_BYTES), "r"(mb)
                : "memory");
        }
        uint32_t done;
        asm volatile(
            "{\n\t.reg .pred p;\n\t"
            "mbarrier.try_wait.parity.acquire.cta.shared::cta.b64 p, [%1], %2;\n\t"
            "selp.b32 %0, 1, 0, p;\n\t}"
            : "=r"(done) : "r"(mb), "r"(0u) : "memory");
        if (!done) {
            asm volatile(
                "{\n\t.reg .pred P1;\n\t"
                "W_%=:\n\t"
                "mbarrier.try_wait.parity.acquire.cta.shared::cta.b64 P1, [%0], %1, 0x989680;\n\t"
                "@P1 bra.uni D_%=;\n\t"
                "bra.uni W_%=;\n\t"
                "D_%=:\n\t}"
                :: "r"(mb), "r"(0u) : "memory");
        }
    } else {
        const int n = rowsHere * ROW_F;
        const float* src = kps + (size_t)rowBase * ROW_F;
        for (int i = tid; i < n; i += THREADS) s[i] = src[i];
        __syncthreads();
    }

    float a0 = 0.0f, a1 = 0.0f;
    if (tid < rowsHere) {
        const float* __restrict__ rp = s + tid * ROW_F;
        int k = 0;

        // ================= PASS 1: joints 0..8 resident =================
        {
            float p[27];
            float g[9];
            #pragma unroll
            for (int c = 0; c < 27; c++) p[c] = rp[c];
            #pragma unroll
            for (int i = 0; i < 9; i++) {
                float x = p[3*i], y = p[3*i+1], z = p[3*i+2];
                float r = fmaf(z, z, fmaf(y, y, x * x));
                g[i] = fmaf(r, -0.5f, 0.0025f);      // 0.25*thr2; FFMA-imm
            }
            // intra pairs among joints 0..8: 36
            #pragma unroll
            for (int i = 0; i < 9; i++)
                #pragma unroll
                for (int j = i + 1; j < 9; j++) {
                    float w = g[i] + g[j];
                    float d = fmaf(p[3*i+2], p[3*j+2],
                              fmaf(p[3*i+1], p[3*j+1],
                              fmaf(p[3*i  ], p[3*j  ], w)));
                    float h = fmaxf(d, 0.0f);
                    if (k & 1) a1 += h; else a0 += h;
                    k++;
                }
            // cross pairs: stream joints 9..16 from SMEM (72 pairs)
            #pragma unroll
            for (int jj = 9; jj < J; jj++) {
                float qx = rp[3*jj], qy = rp[3*jj+1], qz = rp[3*jj+2];
                float qr = fmaf(qz, qz, fmaf(qy, qy, qx * qx));
                float qg = fmaf(qr, -0.5f, 0.0025f);
                #pragma unroll
                for (int i = 0; i < 9; i++) {
                    float w = g[i] + qg;
                    float d = fmaf(p[3*i+2], qz,
                              fmaf(p[3*i+1], qy,
                              fmaf(p[3*i  ], qx, w)));
                    float h = fmaxf(d, 0.0f);
                    if (k & 1) a1 += h; else a0 += h;
                    k++;
                }
            }
        }

        // ================= PASS 2: joints 9..16 resident =================
        {
            float p[24];
            float g[8];
            #pragma unroll
            for (int c = 0; c < 24; c++) p[c] = rp[27 + c];
            #pragma unroll
            for (int i = 0; i < 8; i++) {
                float x = p[3*i], y = p[3*i+1], z = p[3*i+2];
                float r = fmaf(z, z, fmaf(y, y, x * x));
                g[i] = fmaf(r, -0.5f, 0.0025f);
            }
            // intra pairs among joints 9..16: 28
            #pragma unroll
            for (int i = 0; i < 8; i++)
                #pragma unroll
                for (int j = i + 1; j < 8; j++) {
                    float w = g[i] + g[j];
                    float d = fmaf(p[3*i+2], p[3*j+2],
                              fmaf(p[3*i+1], p[3*j+1],
                              fmaf(p[3*i  ], p[3*j  ], w)));
                    float h = fmaxf(d, 0.0f);
                    if (k & 1) a1 += h; else a0 += h;
                    k++;
                }
        }
    }
    // hinge = 2*max(0,d); ordered pairs double again -> x4
    float acc = (a0 + a1) * 4.0f;

    // ---- deterministic block reduction (4 warps) ----
    #pragma unroll
    for (int off = 16; off > 0; off >>= 1)
        acc += __shfl_down_sync(0xFFFFFFFFu, acc, off);
    if ((tid & 31) == 0) wsum[tid >> 5] = acc;
    __syncthreads();

    if (tid == 0) {
        g_partials[blockIdx.x] = (wsum[0] + wsum[1]) + (wsum[2] + wsum[3]);
        __threadfence();
        unsigned int c = atomicInc(&g_done_count, (unsigned int)(nblocks - 1));
        isLast = (c == (unsigned int)(nblocks - 1));
    }
    __syncthreads();

    // ---- last block: vectorized fixed-order final reduction ----
    if (isLast) {
        float v = 0.0f;
        const int nvec = nblocks >> 2;          // 256 for nblocks=1024
        const float4* gp = reinterpret_cast<const float4*>(g_partials);
        #pragma unroll 2
        for (int i = tid; i < nvec; i += THREADS) {
            float4 f = gp[i];
            v += (f.x + f.y) + (f.z + f.w);
        }
        for (int i = (nvec << 2) + tid; i < nblocks; i += THREADS)
            v += g_partials[i];
        #pragma unroll
        for (int off = 16; off > 0; off >>= 1)
            v += __shfl_down_sync(0xFFFFFFFFu, v, off);
        if ((tid & 31) == 0) wsum[tid >> 5] = v;
        __syncthreads();
        if (tid == 0)
            out[0] = ((wsum[0] + wsum[1]) + (wsum[2] + wsum[3])) * invB;
    }
}

extern "C" void kernel_launch(void* const* d_in, const int* in_sizes, int n_in,
                              void* d_out, int out_size) {
    const float* kps = (const float*)d_in[0];
    const int B = in_sizes[0] / ROW_F;
    const int nblocks = (B + ROWS_PER_BLOCK - 1) / ROWS_PER_BLOCK;  // 1024

    sep_loss_fused<<<nblocks, THREADS>>>(kps, B, nblocks, 1.0f / (float)B,
                                         (float*)d_out);
}